// round 15
// baseline (speedup 1.0000x reference)
#include <cuda_runtime.h>
#include <cuda_fp16.h>

#define U_NUMS 100000
#define I_NUMS 50000
#define NTOT   (U_NUMS + I_NUMS)      // 150000 rows
#define HID    64
#define NELEM  (NTOT * HID)
#define NVEC   (NELEM / 4)            // 2,400,000 8B-units for init convert
#define CAP    96                     // per-row bucket capacity (max degree ~50)

// ---- device scratch (zero-initialized at module load) ----
__device__ float4 g_hA[NTOT * 8];     // fp16 x0
__device__ float4 g_hB[NTOT * 8];     // fp16 x1
__device__ float4 g_hC[NTOT * 8];     // fp16 x2
__device__ float4 g_hD[NTOT * 8];     // fp16 x3 = L x2
__device__ int    g_cnt[NTOT];        // starts zero; re-zeroed by finalize
__device__ int2   g_ebuf[NTOT * CAP]; // per-row edges {col*8, half2(v,v) bits}

// fused build: fp16 convert of x0 + bucket fill (2 edges per thread, vector loads)
__global__ void build_kernel(const float4* __restrict__ ue,
                             const float4* __restrict__ ie,
                             const int*   __restrict__ row,
                             const int*   __restrict__ col,
                             const float* __restrict__ val, int E) {
    int i = blockIdx.x * blockDim.x + threadIdx.x;
    if (i < NVEC) {
        const int UV = U_NUMS * HID / 4;
        float4 v = (i < UV) ? __ldg(ue + i) : __ldg(ie + (i - UV));
        float2 pack;
        ((__half2*)&pack)[0] = __floats2half2_rn(v.x, v.y);
        ((__half2*)&pack)[1] = __floats2half2_rn(v.z, v.w);
        ((float2*)g_hA)[i] = pack;
    }
    int e0 = i * 2;
    if (e0 < E) {
        int2   r2 = __ldg((const int2*)(row + e0));
        int2   c2 = __ldg((const int2*)(col + e0));
        float2 v2 = __ldg((const float2*)(val + e0));
        {
            int slot = atomicAdd(&g_cnt[r2.x], 1);
            if (slot < CAP) {
                __half2 hv = __float2half2_rn(v2.x);
                g_ebuf[r2.x * CAP + slot] =
                    make_int2(c2.x << 3, (int)*(const unsigned*)&hv);
            }
        }
        if (e0 + 1 < E) {
            int slot = atomicAdd(&g_cnt[r2.y], 1);
            if (slot < CAP) {
                __half2 hv = __float2half2_rn(v2.y);
                g_ebuf[r2.y * CAP + slot] =
                    make_int2(c2.y << 3, (int)*(const unsigned*)&hv);
            }
        }
    }
}

// fp16 fma of one gathered float4 (4 half2) into the 4 half2 row accumulators
#define EDGE_HFMA(vbits, rr)                                                 \
    do {                                                                     \
        __half2 vv = *(const __half2*)&(vbits);                              \
        const __half2* h = (const __half2*)&(rr);                            \
        ha0 = __hfma2(h[0], vv, ha0);                                        \
        ha1 = __hfma2(h[1], vv, ha1);                                        \
        ha2 = __hfma2(h[2], vv, ha2);                                        \
        ha3 = __hfma2(h[3], vv, ha3);                                        \
    } while (0)

// ---- bucket gather SpMM: hy = L hx (all fp16, R12 structure: min traffic) ----
__global__ void __launch_bounds__(256, 8) gather_kernel(
                              const float4* __restrict__ hx,
                              float4*       __restrict__ hy) {
    int t  = threadIdx.x;
    int ch = t & 7;
    int r  = blockIdx.x * (blockDim.x >> 3) + (t >> 3);
    if (r >= NTOT) return;

    int cnt = __ldg(&g_cnt[r]);
    cnt = (cnt > CAP) ? CAP : cnt;
    const int2* eb = g_ebuf + r * CAP;

    const __half2 hz = __float2half2_rn(0.f);
    __half2 ha0 = hz, ha1 = hz, ha2 = hz, ha3 = hz;

    int j = 0;
    for (; j + 3 < cnt; j += 4) {
        int4 p0 = __ldg((const int4*)(eb + j));
        int4 p1 = __ldg((const int4*)(eb + j + 2));
        float4 r0 = __ldg(hx + p0.x + ch);
        float4 r1 = __ldg(hx + p0.z + ch);
        float4 r2 = __ldg(hx + p1.x + ch);
        float4 r3 = __ldg(hx + p1.z + ch);
        EDGE_HFMA(p0.y, r0);
        EDGE_HFMA(p0.w, r1);
        EDGE_HFMA(p1.y, r2);
        EDGE_HFMA(p1.w, r3);
    }
    for (; j < cnt; j++) {
        int2 e0 = __ldg(eb + j);
        float4 r0 = __ldg(hx + e0.x + ch);
        EDGE_HFMA(e0.y, r0);
    }

    float4 pack;
    ((__half2*)&pack)[0] = ha0;
    ((__half2*)&pack)[1] = ha1;
    ((__half2*)&pack)[2] = ha2;
    ((__half2*)&pack)[3] = ha3;
    hy[r * 8 + ch] = pack;
}

// ---- pure streaming finalize: out = 0.25*(x0 + x1 + x2 + x3); reset g_cnt ----
__global__ void __launch_bounds__(256) finalize_kernel(float4* __restrict__ out) {
    int i = blockIdx.x * blockDim.x + threadIdx.x;   // 0 .. NTOT*8-1
    if (i < NTOT) g_cnt[i] = 0;                      // reset for next replay
    if (i >= NTOT * 8) return;

    float4 qa = g_hA[i];
    float4 qb = g_hB[i];
    float4 qc = g_hC[i];
    float4 qd = g_hD[i];
    const __half2* ha = (const __half2*)&qa;
    const __half2* hb = (const __half2*)&qb;
    const __half2* hc = (const __half2*)&qc;
    const __half2* hd = (const __half2*)&qd;

    float4 o0, o1;
    {
        float2 a = __half22float2(ha[0]), b = __half22float2(hb[0]);
        float2 c = __half22float2(hc[0]), d = __half22float2(hd[0]);
        o0.x = (a.x + b.x + c.x + d.x) * 0.25f;
        o0.y = (a.y + b.y + c.y + d.y) * 0.25f;
    }
    {
        float2 a = __half22float2(ha[1]), b = __half22float2(hb[1]);
        float2 c = __half22float2(hc[1]), d = __half22float2(hd[1]);
        o0.z = (a.x + b.x + c.x + d.x) * 0.25f;
        o0.w = (a.y + b.y + c.y + d.y) * 0.25f;
    }
    {
        float2 a = __half22float2(ha[2]), b = __half22float2(hb[2]);
        float2 c = __half22float2(hc[2]), d = __half22float2(hd[2]);
        o1.x = (a.x + b.x + c.x + d.x) * 0.25f;
        o1.y = (a.y + b.y + c.y + d.y) * 0.25f;
    }
    {
        float2 a = __half22float2(ha[3]), b = __half22float2(hb[3]);
        float2 c = __half22float2(hc[3]), d = __half22float2(hd[3]);
        o1.z = (a.x + b.x + c.x + d.x) * 0.25f;
        o1.w = (a.y + b.y + c.y + d.y) * 0.25f;
    }
    out[i * 2]     = o0;
    out[i * 2 + 1] = o1;
}

extern "C" void kernel_launch(void* const* d_in, const int* in_sizes, int n_in,
                              void* d_out, int out_size) {
    const float4* ue  = (const float4*)d_in[0];
    const float4* ie  = (const float4*)d_in[1];
    const int*    row = (const int*)  d_in[2];
    const int*    col = (const int*)  d_in[3];
    const float*  val = (const float*)d_in[4];
    float4* out = (float4*)d_out;

    int E = in_sizes[2];

    void *pa = nullptr, *pb = nullptr, *pc = nullptr, *pd = nullptr;
    cudaGetSymbolAddress(&pa, g_hA);
    cudaGetSymbolAddress(&pb, g_hB);
    cudaGetSymbolAddress(&pc, g_hC);
    cudaGetSymbolAddress(&pd, g_hD);
    float4* hA = (float4*)pa;
    float4* hB = (float4*)pb;
    float4* hC = (float4*)pc;
    float4* hD = (float4*)pd;

    const int TB = 256;
    int epairs       = (E + 1) / 2;
    int build_n      = (NVEC > epairs) ? NVEC : epairs;
    int build_blocks = (build_n + TB - 1) / TB;
    int row_blocks   = (NTOT + (TB / 8) - 1) / (TB / 8);     // 32 rows per block
    int fin_blocks   = (NTOT * 8 + TB - 1) / TB;

    // fused build: convert x0 to fp16 + bucket-fill edges (g_cnt zeroed invariant)
    build_kernel<<<build_blocks, TB>>>(ue, ie, row, col, val, E);

    // three identical gathers (random-access regime), all-fp16 accumulate
    gather_kernel<<<row_blocks, TB>>>(hA, hB);   // x1 = L x0
    gather_kernel<<<row_blocks, TB>>>(hB, hC);   // x2 = L x1
    gather_kernel<<<row_blocks, TB>>>(hC, hD);   // x3 = L x2

    // streaming finalize (bandwidth regime): out = 0.25 * (x0+x1+x2+x3)
    finalize_kernel<<<fin_blocks, TB>>>(out);
}

// round 16
// speedup vs baseline: 1.3279x; 1.3279x over previous
#include <cuda_runtime.h>
#include <cuda_fp16.h>

#define U_NUMS 100000
#define I_NUMS 50000
#define NTOT   (U_NUMS + I_NUMS)      // 150000 rows
#define HID    64
#define NELEM  (NTOT * HID)
#define NVEC   (NELEM / 4)            // 2,400,000 8B-units for init convert
#define CAP    96                     // per-row bucket capacity (max degree ~50)

// ---- device scratch (zero-initialized at module load) ----
__device__ float4 g_hA[NTOT * 8];     // fp16 x0
__device__ float4 g_hB[NTOT * 8];     // fp16 x1
__device__ float4 g_hC[NTOT * 8];     // fp16 x2
__device__ float4 g_hD[NTOT * 8];     // fp16 x3 = L x2
__device__ int    g_cnt[NTOT];        // starts zero; re-zeroed by finalize
__device__ int2   g_ebuf[NTOT * CAP]; // per-row edges {col*8, half2(v,v) bits}

// fused build: fp16 convert of x0 + bucket fill (2 edges per thread, vector loads)
__global__ void build_kernel(const float4* __restrict__ ue,
                             const float4* __restrict__ ie,
                             const int*   __restrict__ row,
                             const int*   __restrict__ col,
                             const float* __restrict__ val, int E) {
    int i = blockIdx.x * blockDim.x + threadIdx.x;
    if (i < NVEC) {
        const int UV = U_NUMS * HID / 4;
        float4 v = (i < UV) ? __ldg(ue + i) : __ldg(ie + (i - UV));
        float2 pack;
        ((__half2*)&pack)[0] = __floats2half2_rn(v.x, v.y);
        ((__half2*)&pack)[1] = __floats2half2_rn(v.z, v.w);
        ((float2*)g_hA)[i] = pack;
    }
    int e0 = i * 2;
    if (e0 < E) {
        int2   r2 = __ldg((const int2*)(row + e0));
        int2   c2 = __ldg((const int2*)(col + e0));
        float2 v2 = __ldg((const float2*)(val + e0));
        {
            int slot = atomicAdd(&g_cnt[r2.x], 1);
            if (slot < CAP) {
                __half2 hv = __float2half2_rn(v2.x);
                g_ebuf[r2.x * CAP + slot] =
                    make_int2(c2.x << 3, (int)*(const unsigned*)&hv);
            }
        }
        if (e0 + 1 < E) {
            int slot = atomicAdd(&g_cnt[r2.y], 1);
            if (slot < CAP) {
                __half2 hv = __float2half2_rn(v2.y);
                g_ebuf[r2.y * CAP + slot] =
                    make_int2(c2.y << 3, (int)*(const unsigned*)&hv);
            }
        }
    }
}

// fp16 fma of one gathered float4 (4 half2) into the 4 half2 row accumulators
#define EDGE_HFMA(vbits, rr)                                                 \
    do {                                                                     \
        __half2 vv = *(const __half2*)&(vbits);                              \
        const __half2* h = (const __half2*)&(rr);                            \
        ha0 = __hfma2(h[0], vv, ha0);                                        \
        ha1 = __hfma2(h[1], vv, ha1);                                        \
        ha2 = __hfma2(h[2], vv, ha2);                                        \
        ha3 = __hfma2(h[3], vv, ha3);                                        \
    } while (0)

// ---- bucket gather SpMM: hy = L hx (all fp16, minimal-traffic loop) ----
__global__ void __launch_bounds__(256, 8) gather_kernel(
                              const float4* __restrict__ hx,
                              float4*       __restrict__ hy) {
    int t  = threadIdx.x;
    int ch = t & 7;
    int r  = blockIdx.x * (blockDim.x >> 3) + (t >> 3);
    if (r >= NTOT) return;

    int cnt = __ldg(&g_cnt[r]);
    cnt = (cnt > CAP) ? CAP : cnt;
    const int2* eb = g_ebuf + r * CAP;

    const __half2 hz = __float2half2_rn(0.f);
    __half2 ha0 = hz, ha1 = hz, ha2 = hz, ha3 = hz;

    int j = 0;
    for (; j + 3 < cnt; j += 4) {
        int4 p0 = __ldg((const int4*)(eb + j));
        int4 p1 = __ldg((const int4*)(eb + j + 2));
        float4 r0 = __ldg(hx + p0.x + ch);
        float4 r1 = __ldg(hx + p0.z + ch);
        float4 r2 = __ldg(hx + p1.x + ch);
        float4 r3 = __ldg(hx + p1.z + ch);
        EDGE_HFMA(p0.y, r0);
        EDGE_HFMA(p0.w, r1);
        EDGE_HFMA(p1.y, r2);
        EDGE_HFMA(p1.w, r3);
    }
    for (; j < cnt; j++) {
        int2 e0 = __ldg(eb + j);
        float4 r0 = __ldg(hx + e0.x + ch);
        EDGE_HFMA(e0.y, r0);
    }

    float4 pack;
    ((__half2*)&pack)[0] = ha0;
    ((__half2*)&pack)[1] = ha1;
    ((__half2*)&pack)[2] = ha2;
    ((__half2*)&pack)[3] = ha3;
    hy[r * 8 + ch] = pack;
}

// ---- pure streaming finalize: out = 0.25*(x0 + x1 + x2 + x3); reset g_cnt ----
__global__ void __launch_bounds__(256) finalize_kernel(float4* __restrict__ out) {
    int i = blockIdx.x * blockDim.x + threadIdx.x;   // 0 .. NTOT*8-1
    if (i < NTOT) g_cnt[i] = 0;                      // reset for next replay
    if (i >= NTOT * 8) return;

    float4 qa = g_hA[i];
    float4 qb = g_hB[i];
    float4 qc = g_hC[i];
    float4 qd = g_hD[i];
    const __half2* ha = (const __half2*)&qa;
    const __half2* hb = (const __half2*)&qb;
    const __half2* hc = (const __half2*)&qc;
    const __half2* hd = (const __half2*)&qd;

    float4 o0, o1;
    {
        float2 a = __half22float2(ha[0]), b = __half22float2(hb[0]);
        float2 c = __half22float2(hc[0]), d = __half22float2(hd[0]);
        o0.x = (a.x + b.x + c.x + d.x) * 0.25f;
        o0.y = (a.y + b.y + c.y + d.y) * 0.25f;
    }
    {
        float2 a = __half22float2(ha[1]), b = __half22float2(hb[1]);
        float2 c = __half22float2(hc[1]), d = __half22float2(hd[1]);
        o0.z = (a.x + b.x + c.x + d.x) * 0.25f;
        o0.w = (a.y + b.y + c.y + d.y) * 0.25f;
    }
    {
        float2 a = __half22float2(ha[2]), b = __half22float2(hb[2]);
        float2 c = __half22float2(hc[2]), d = __half22float2(hd[2]);
        o1.x = (a.x + b.x + c.x + d.x) * 0.25f;
        o1.y = (a.y + b.y + c.y + d.y) * 0.25f;
    }
    {
        float2 a = __half22float2(ha[3]), b = __half22float2(hb[3]);
        float2 c = __half22float2(hc[3]), d = __half22float2(hd[3]);
        o1.z = (a.x + b.x + c.x + d.x) * 0.25f;
        o1.w = (a.y + b.y + c.y + d.y) * 0.25f;
    }
    out[i * 2]     = o0;
    out[i * 2 + 1] = o1;
}

extern "C" void kernel_launch(void* const* d_in, const int* in_sizes, int n_in,
                              void* d_out, int out_size) {
    const float4* ue  = (const float4*)d_in[0];
    const float4* ie  = (const float4*)d_in[1];
    const int*    row = (const int*)  d_in[2];
    const int*    col = (const int*)  d_in[3];
    const float*  val = (const float*)d_in[4];
    float4* out = (float4*)d_out;

    int E = in_sizes[2];

    void *pa = nullptr, *pb = nullptr, *pc = nullptr, *pd = nullptr;
    cudaGetSymbolAddress(&pa, g_hA);
    cudaGetSymbolAddress(&pb, g_hB);
    cudaGetSymbolAddress(&pc, g_hC);
    cudaGetSymbolAddress(&pd, g_hD);
    float4* hA = (float4*)pa;
    float4* hB = (float4*)pb;
    float4* hC = (float4*)pc;
    float4* hD = (float4*)pd;

    const int TB = 256;
    int epairs       = (E + 1) / 2;
    int build_n      = (NVEC > epairs) ? NVEC : epairs;
    int build_blocks = (build_n + TB - 1) / TB;
    int row_blocks   = (NTOT + (TB / 8) - 1) / (TB / 8);     // 32 rows per block
    int fin_blocks   = (NTOT * 8 + TB - 1) / TB;

    // fused build: convert x0 to fp16 + bucket-fill edges (g_cnt zeroed invariant)
    build_kernel<<<build_blocks, TB>>>(ue, ie, row, col, val, E);

    // three identical gathers (random-access regime), all-fp16 accumulate
    gather_kernel<<<row_blocks, TB>>>(hA, hB);   // x1 = L x0
    gather_kernel<<<row_blocks, TB>>>(hB, hC);   // x2 = L x1
    gather_kernel<<<row_blocks, TB>>>(hC, hD);   // x3 = L x2

    // streaming finalize (bandwidth regime): out = 0.25 * (x0+x1+x2+x3)
    finalize_kernel<<<fin_blocks, TB>>>(out);
}

// round 17
// speedup vs baseline: 1.3458x; 1.0134x over previous
#include <cuda_runtime.h>
#include <cuda_fp16.h>

#define U_NUMS 100000
#define I_NUMS 50000
#define NTOT   (U_NUMS + I_NUMS)      // 150000 rows
#define HID    64
#define NELEM  (NTOT * HID)
#define NVEC   (NELEM / 4)            // 2,400,000 8B-units for init convert
#define CAP    96                     // per-row bucket capacity (max degree ~50)

// ---- device scratch (zero-initialized at module load) ----
__device__ float4 g_hA[NTOT * 8];     // fp16 x0
__device__ float4 g_hB[NTOT * 8];     // fp16 x1
__device__ float4 g_hC[NTOT * 8];     // fp16 x2
__device__ float4 g_hD[NTOT * 8];     // fp16 x3 = L x2
__device__ int    g_cnt[NTOT];        // starts zero; re-zeroed by finalize
__device__ int2   g_ebuf[NTOT * CAP]; // per-row edges {col*8, half2(v,v) bits}

__device__ __forceinline__ void fill_one(int r, int c, float v) {
    int slot = atomicAdd(&g_cnt[r], 1);
    if (slot < CAP) {
        __half2 hv = __float2half2_rn(v);
        g_ebuf[r * CAP + slot] = make_int2(c << 3, (int)*(const unsigned*)&hv);
    }
}

// role-split build: blocks with (blockIdx.x % 6 == 5) fill edges (4/thread,
// latency regime); the other 5/6 convert x0 to fp16 (streaming regime).
// Both regimes run concurrently on different SMs inside one launch.
__global__ void build_kernel(const float4* __restrict__ ue,
                             const float4* __restrict__ ie,
                             const int*   __restrict__ row,
                             const int*   __restrict__ col,
                             const float* __restrict__ val, int E) {
    int b    = blockIdx.x;
    int role = b % 6;
    if (role == 5) {
        // ---- edge fill: 4 edges per thread, vector loads, independent atomics
        int fb = b / 6;
        int e0 = (fb * 256 + (int)threadIdx.x) * 4;
        if (e0 >= E) return;
        if (e0 + 3 < E) {
            int4   r4 = __ldg((const int4*)  (row + e0));
            int4   c4 = __ldg((const int4*)  (col + e0));
            float4 v4 = __ldg((const float4*)(val + e0));
            fill_one(r4.x, c4.x, v4.x);
            fill_one(r4.y, c4.y, v4.y);
            fill_one(r4.z, c4.z, v4.z);
            fill_one(r4.w, c4.w, v4.w);
        } else {
            for (int e = e0; e < E; e++)
                fill_one(__ldg(row + e), __ldg(col + e), __ldg(val + e));
        }
    } else {
        // ---- x0 convert: fp32 -> fp16, streaming
        int cb = (b / 6) * 5 + role;
        int i  = cb * 256 + (int)threadIdx.x;
        if (i >= NVEC) return;
        const int UV = U_NUMS * HID / 4;
        float4 v = (i < UV) ? __ldg(ue + i) : __ldg(ie + (i - UV));
        float2 pack;
        ((__half2*)&pack)[0] = __floats2half2_rn(v.x, v.y);
        ((__half2*)&pack)[1] = __floats2half2_rn(v.z, v.w);
        ((float2*)g_hA)[i] = pack;
    }
}

// fp16 fma of one gathered float4 (4 half2) into the 4 half2 row accumulators
#define EDGE_HFMA(vbits, rr)                                                 \
    do {                                                                     \
        __half2 vv = *(const __half2*)&(vbits);                              \
        const __half2* h = (const __half2*)&(rr);                            \
        ha0 = __hfma2(h[0], vv, ha0);                                        \
        ha1 = __hfma2(h[1], vv, ha1);                                        \
        ha2 = __hfma2(h[2], vv, ha2);                                        \
        ha3 = __hfma2(h[3], vv, ha3);                                        \
    } while (0)

// ---- bucket gather SpMM: hy = L hx (all fp16, minimal-traffic loop) ----
__global__ void __launch_bounds__(256, 8) gather_kernel(
                              const float4* __restrict__ hx,
                              float4*       __restrict__ hy) {
    int t  = threadIdx.x;
    int ch = t & 7;
    int r  = blockIdx.x * (blockDim.x >> 3) + (t >> 3);
    if (r >= NTOT) return;

    int cnt = __ldg(&g_cnt[r]);
    cnt = (cnt > CAP) ? CAP : cnt;
    const int2* eb = g_ebuf + r * CAP;

    const __half2 hz = __float2half2_rn(0.f);
    __half2 ha0 = hz, ha1 = hz, ha2 = hz, ha3 = hz;

    int j = 0;
    for (; j + 3 < cnt; j += 4) {
        int4 p0 = __ldg((const int4*)(eb + j));
        int4 p1 = __ldg((const int4*)(eb + j + 2));
        float4 r0 = __ldg(hx + p0.x + ch);
        float4 r1 = __ldg(hx + p0.z + ch);
        float4 r2 = __ldg(hx + p1.x + ch);
        float4 r3 = __ldg(hx + p1.z + ch);
        EDGE_HFMA(p0.y, r0);
        EDGE_HFMA(p0.w, r1);
        EDGE_HFMA(p1.y, r2);
        EDGE_HFMA(p1.w, r3);
    }
    for (; j < cnt; j++) {
        int2 e0 = __ldg(eb + j);
        float4 r0 = __ldg(hx + e0.x + ch);
        EDGE_HFMA(e0.y, r0);
    }

    float4 pack;
    ((__half2*)&pack)[0] = ha0;
    ((__half2*)&pack)[1] = ha1;
    ((__half2*)&pack)[2] = ha2;
    ((__half2*)&pack)[3] = ha3;
    hy[r * 8 + ch] = pack;
}

// ---- pure streaming finalize: out = 0.25*(x0 + x1 + x2 + x3); reset g_cnt ----
__global__ void __launch_bounds__(256) finalize_kernel(float4* __restrict__ out) {
    int i = blockIdx.x * blockDim.x + threadIdx.x;   // 0 .. NTOT*8-1
    if (i < NTOT) g_cnt[i] = 0;                      // reset for next replay
    if (i >= NTOT * 8) return;

    float4 qa = g_hA[i];
    float4 qb = g_hB[i];
    float4 qc = g_hC[i];
    float4 qd = g_hD[i];
    const __half2* ha = (const __half2*)&qa;
    const __half2* hb = (const __half2*)&qb;
    const __half2* hc = (const __half2*)&qc;
    const __half2* hd = (const __half2*)&qd;

    float4 o0, o1;
    {
        float2 a = __half22float2(ha[0]), b = __half22float2(hb[0]);
        float2 c = __half22float2(hc[0]), d = __half22float2(hd[0]);
        o0.x = (a.x + b.x + c.x + d.x) * 0.25f;
        o0.y = (a.y + b.y + c.y + d.y) * 0.25f;
    }
    {
        float2 a = __half22float2(ha[1]), b = __half22float2(hb[1]);
        float2 c = __half22float2(hc[1]), d = __half22float2(hd[1]);
        o0.z = (a.x + b.x + c.x + d.x) * 0.25f;
        o0.w = (a.y + b.y + c.y + d.y) * 0.25f;
    }
    {
        float2 a = __half22float2(ha[2]), b = __half22float2(hb[2]);
        float2 c = __half22float2(hc[2]), d = __half22float2(hd[2]);
        o1.x = (a.x + b.x + c.x + d.x) * 0.25f;
        o1.y = (a.y + b.y + c.y + d.y) * 0.25f;
    }
    {
        float2 a = __half22float2(ha[3]), b = __half22float2(hb[3]);
        float2 c = __half22float2(hc[3]), d = __half22float2(hd[3]);
        o1.z = (a.x + b.x + c.x + d.x) * 0.25f;
        o1.w = (a.y + b.y + c.y + d.y) * 0.25f;
    }
    out[i * 2]     = o0;
    out[i * 2 + 1] = o1;
}

extern "C" void kernel_launch(void* const* d_in, const int* in_sizes, int n_in,
                              void* d_out, int out_size) {
    const float4* ue  = (const float4*)d_in[0];
    const float4* ie  = (const float4*)d_in[1];
    const int*    row = (const int*)  d_in[2];
    const int*    col = (const int*)  d_in[3];
    const float*  val = (const float*)d_in[4];
    float4* out = (float4*)d_out;

    int E = in_sizes[2];

    void *pa = nullptr, *pb = nullptr, *pc = nullptr, *pd = nullptr;
    cudaGetSymbolAddress(&pa, g_hA);
    cudaGetSymbolAddress(&pb, g_hB);
    cudaGetSymbolAddress(&pc, g_hC);
    cudaGetSymbolAddress(&pd, g_hD);
    float4* hA = (float4*)pa;
    float4* hB = (float4*)pb;
    float4* hC = (float4*)pc;
    float4* hD = (float4*)pd;

    const int TB = 256;
    // role-split build grid: 1 fill block per 5 convert blocks (mod-6 cycle)
    int fill_blocks = ((E + 3) / 4 + TB - 1) / TB;           // 1954 for E=2M
    int conv_blocks = (NVEC + TB - 1) / TB;                  // 9375
    int cycles      = fill_blocks;
    int need_cyc    = (conv_blocks + 4) / 5;
    if (need_cyc > cycles) cycles = need_cyc;
    int build_grid  = cycles * 6;

    int row_blocks = (NTOT + (TB / 8) - 1) / (TB / 8);       // 32 rows per block
    int fin_blocks = (NTOT * 8 + TB - 1) / TB;

    // fused role-split build (g_cnt zeroed invariant)
    build_kernel<<<build_grid, TB>>>(ue, ie, row, col, val, E);

    // three identical gathers (random-access regime), all-fp16 accumulate
    gather_kernel<<<row_blocks, TB>>>(hA, hB);   // x1 = L x0
    gather_kernel<<<row_blocks, TB>>>(hB, hC);   // x2 = L x1
    gather_kernel<<<row_blocks, TB>>>(hC, hD);   // x3 = L x2

    // streaming finalize (bandwidth regime): out = 0.25 * (x0+x1+x2+x3)
    finalize_kernel<<<fin_blocks, TB>>>(out);
}